// round 1
// baseline (speedup 1.0000x reference)
#include <cuda_runtime.h>
#include <cstdint>

// VectorQuantizerEMA forward:
//   inputs [64,1024,64] f32, embedding [512,64] f32
//   out = [loss(1) | quantized_st(65536*64) | perplexity(1) | indices(65536)] f32
//
// Distances replicated exactly as reference fp32 formula:
//   d_k = fl( fl(A + b_k) - fl(2 * dot_k) )
//   A   = sum_i fl(x_i^2)      (square rounded, then sequential sum)
//   b_k = sum_i fl(e_ki^2)
//   dot = fp32 fma chain over i = 0..63
// Argmin ties broken by lowest index (matches jnp.argmin).

#define KN 512
#define DN 64
#define TPG 8           // tokens per warp-group iteration
#define NWARP 8         // warps per block (256 threads)
#define NBLK 148

__device__ double       g_err_sum;
__device__ unsigned int g_counts[KN];

__global__ void vq_zero() {
    int t = threadIdx.x;
    if (t == 0) g_err_sum = 0.0;
    if (t < KN) g_counts[t] = 0u;
}

extern __shared__ float smem_dyn[];

__global__ __launch_bounds__(NWARP * 32, 1)
void vq_main(const float* __restrict__ x, const float* __restrict__ emb,
             float* __restrict__ out_q, float* __restrict__ out_idx, int ntok)
{
    // smem layout
    float* eT = smem_dyn;                       // [64][512]  transposed embedding
    float* bn = eT + KN * DN;                   // [512]      ||e_k||^2
    float* xs = bn + KN;                        // [NWARP][TPG*64] staged tokens
    unsigned int* shist = (unsigned int*)(xs + NWARP * TPG * DN); // [512]

    const int tid  = threadIdx.x;
    const int lane = tid & 31;
    const int warp = tid >> 5;

    // Load embedding transposed: eT[i][k] = emb[k][i]
    for (int t = tid; t < KN * DN; t += blockDim.x) {
        int k = t >> 6, i = t & 63;
        eT[i * KN + k] = emb[t];
    }
    // Row norms (square rounded, sequential sum — mirrors emb*emb then sum)
    for (int k = tid; k < KN; k += blockDim.x) {
        const float* ep = emb + k * DN;
        float s = 0.f;
        #pragma unroll
        for (int i = 0; i < DN; i++) {
            float sq = __fmul_rn(ep[i], ep[i]);
            s = __fadd_rn(s, sq);
        }
        bn[k] = s;
    }
    for (int t = tid; t < KN; t += blockDim.x) shist[t] = 0u;
    __syncthreads();

    double werr = 0.0;

    const int gwarp   = blockIdx.x * NWARP + warp;
    const int ngroups = ntok / TPG;
    const int gstride = gridDim.x * NWARP;
    float* xw = xs + warp * (TPG * DN);

    for (int g = gwarp; g < ngroups; g += gstride) {
        const int tok0 = g * TPG;
        const float* xp = x + (size_t)tok0 * DN;

        // Stage TPG*64 = 512 floats, coalesced
        #pragma unroll
        for (int m = 0; m < (TPG * DN) / 32; m++)
            xw[m * 32 + lane] = xp[m * 32 + lane];
        __syncwarp();

        // Accumulators: lane covers k = j*64 + 2*lane + {0,1}, j = 0..7
        unsigned long long acc[TPG][8];
        float A[TPG];
        #pragma unroll
        for (int tt = 0; tt < TPG; tt++) {
            A[tt] = 0.f;
            #pragma unroll
            for (int j = 0; j < 8; j++) acc[tt][j] = 0ULL;
        }

        #pragma unroll 2
        for (int i = 0; i < DN; i++) {
            const float* erow = eT + i * KN + 2 * lane;
            unsigned long long e2[8];
            #pragma unroll
            for (int j = 0; j < 8; j++)
                e2[j] = *(const unsigned long long*)(erow + j * 64);

            #pragma unroll
            for (int tt = 0; tt < TPG; tt++) {
                float xv = xw[tt * DN + i];           // warp broadcast
                unsigned long long xvv;
                asm("mov.b64 %0, {%1, %1};" : "=l"(xvv) : "r"(__float_as_uint(xv)));
                float sq = __fmul_rn(xv, xv);
                A[tt] = __fadd_rn(A[tt], sq);
                #pragma unroll
                for (int j = 0; j < 8; j++)
                    asm("fma.rn.f32x2 %0, %1, %2, %0;"
                        : "+l"(acc[tt][j]) : "l"(xvv), "l"(e2[j]));
            }
        }

        // Epilogue per token: argmin, gather, outputs
        #pragma unroll
        for (int tt = 0; tt < TPG; tt++) {
            float bestd = 3.0e38f;
            int   bestk = 0x7fffffff;
            #pragma unroll
            for (int j = 0; j < 8; j++) {
                unsigned int u0, u1;
                asm("mov.b64 {%0, %1}, %2;" : "=r"(u0), "=r"(u1) : "l"(acc[tt][j]));
                float c0 = __uint_as_float(u0);
                float c1 = __uint_as_float(u1);
                int k0 = j * 64 + 2 * lane;
                float d0 = __fsub_rn(__fadd_rn(A[tt], bn[k0]),     __fmul_rn(2.0f, c0));
                float d1 = __fsub_rn(__fadd_rn(A[tt], bn[k0 + 1]), __fmul_rn(2.0f, c1));
                if (d0 < bestd) { bestd = d0; bestk = k0; }
                if (d1 < bestd) { bestd = d1; bestk = k0 + 1; }
            }
            // Warp argmin with lowest-index tie-break
            #pragma unroll
            for (int off = 16; off > 0; off >>= 1) {
                float od = __shfl_xor_sync(0xffffffffu, bestd, off);
                int   ok = __shfl_xor_sync(0xffffffffu, bestk, off);
                if (od < bestd || (od == bestd && ok < bestk)) { bestd = od; bestk = ok; }
            }

            int tok = tok0 + tt;
            const float* eqr = emb + bestk * DN;
            float x0 = xw[tt * DN + lane];
            float x1 = xw[tt * DN + 32 + lane];
            float q0 = __ldg(eqr + lane);
            float q1 = __ldg(eqr + 32 + lane);
            float dq0 = __fsub_rn(q0, x0);
            float dq1 = __fsub_rn(q1, x1);
            // straight-through: x + (q - x)
            out_q[(size_t)tok * DN + lane]      = __fadd_rn(x0, dq0);
            out_q[(size_t)tok * DN + 32 + lane] = __fadd_rn(x1, dq1);

            float errv = __fmaf_rn(dq0, dq0, __fmul_rn(dq1, dq1));
            #pragma unroll
            for (int off = 16; off > 0; off >>= 1)
                errv += __shfl_xor_sync(0xffffffffu, errv, off);
            if (lane == 0) {
                out_idx[tok] = (float)bestk;
                atomicAdd(&shist[bestk], 1u);
                werr += (double)errv;
            }
        }
    }

    if (lane == 0) atomicAdd(&g_err_sum, werr);
    __syncthreads();
    for (int t = tid; t < KN; t += blockDim.x) {
        unsigned int c = shist[t];
        if (c) atomicAdd(&g_counts[t], c);
    }
}

__global__ void vq_fin(float* __restrict__ out_loss, float* __restrict__ out_perp, int ntok)
{
    if (threadIdx.x == 0) {
        double total = (double)ntok * (double)DN;
        float m = (float)(g_err_sum / total);          // q_latent == e_latent numerically
        out_loss[0] = __fadd_rn(m, __fmul_rn(0.25f, m));

        float s = 0.f;
        float invN = 1.0f / (float)ntok;
        for (int k = 0; k < KN; k++) {
            float p = (float)g_counts[k] * invN;
            s = __fmaf_rn(p, logf(__fadd_rn(p, 1e-10f)), s);
        }
        out_perp[0] = expf(-s);
    }
}

extern "C" void kernel_launch(void* const* d_in, const int* in_sizes, int n_in,
                              void* d_out, int out_size)
{
    const float* x   = (const float*)d_in[0];
    const float* emb = (const float*)d_in[1];
    const int ntok = in_sizes[0] / DN;   // 65536

    float* out      = (float*)d_out;
    float* out_q    = out + 1;
    float* out_perp = out + 1 + (size_t)ntok * DN;
    float* out_idx  = out + 2 + (size_t)ntok * DN;

    size_t smem = (size_t)(KN * DN + KN + NWARP * TPG * DN) * sizeof(float)
                + (size_t)KN * sizeof(unsigned int);
    cudaFuncSetAttribute(vq_main, cudaFuncAttributeMaxDynamicSharedMemorySize, (int)smem);

    vq_zero<<<1, 512>>>();
    vq_main<<<NBLK, NWARP * 32, smem>>>(x, emb, out_q, out_idx, ntok);
    vq_fin<<<1, 32>>>(out, out_perp, ntok);
}